// round 1
// baseline (speedup 1.0000x reference)
#include <cuda_runtime.h>

// ---------------- problem constants ----------------
#define BATCH 4
#define CIN   320
#define COUT  320
#define HH    64
#define WW    64
#define HW    4096           // 64*64
#define K9    9
#define CK    2880           // CIN*9
#define CAT2  640            // 2*COUT
#define NPIX  4096           // per-batch N

// ---------------- device scratch (static; no allocs) ----------------
__device__ float g_bconv[(size_t)BATCH * CK * HW];   // im2col of conv patches   (~189MB)
__device__ float g_bdef [(size_t)BATCH * CK * HW];   // im2col of deformable     (~189MB)
__device__ float g_cat  [(size_t)BATCH * CAT2 * HW]; // [dconv(0..319) ; h(320..639)]
__device__ float g_down [(size_t)BATCH * COUT * HW];
__device__ int   g_gidx [K9 * HW * 4];
__device__ float g_gw   [K9 * HW * 4];

// ---------------- kernel 1: gather precompute ----------------
__global__ void precompute_gather(const float* __restrict__ offset) {
    int t = blockIdx.x * blockDim.x + threadIdx.x;   // t = k*4096 + p
    if (t >= K9 * HW) return;
    int k = t >> 12;
    int p = t & 4095;
    int r = p >> 6, c = p & 63;
    float dy = offset[((k * 2 + 0) << 12) + p];
    float dx = offset[((k * 2 + 1) << 12) + p];
    float py = ((float)r - 1.0f + (float)(k / 3)) + dy;
    float px = ((float)c - 1.0f + (float)(k % 3)) + dx;
    float y0f = floorf(py), x0f = floorf(px);
    int y0 = (int)y0f, x0 = (int)x0f;
    float wy = py - y0f, wx = px - x0f;
    float ww[4] = { (1.f - wy) * (1.f - wx), (1.f - wy) * wx,
                    wy * (1.f - wx),         wy * wx };
#pragma unroll
    for (int j = 0; j < 4; j++) {
        int yy = y0 + (j >> 1);
        int xx = x0 + (j & 1);
        bool valid = (yy >= 0) && (yy < HH) && (xx >= 0) && (xx < WW);
        int yc = min(max(yy, 0), HH - 1);
        int xc = min(max(xx, 0), WW - 1);
        g_gidx[t * 4 + j] = yc * WW + xc;
        g_gw  [t * 4 + j] = valid ? ww[j] : 0.0f;
    }
}

// ---------------- kernel 2: conv im2col ----------------
// grid (HW/256, CK, BATCH)
__global__ void im2col_conv(const float* __restrict__ x) {
    int p  = blockIdx.x * blockDim.x + threadIdx.x;  // 0..4095
    int ck = blockIdx.y;
    int b  = blockIdx.z;
    int k = ck % 9, c = ck / 9;
    int r = (p >> 6) + k / 3 - 1;
    int q = (p & 63) + k % 3 - 1;
    float v = 0.f;
    if ((unsigned)r < (unsigned)HH && (unsigned)q < (unsigned)WW)
        v = x[(((size_t)b * CIN + c) << 12) + (r << 6) + q];
    g_bconv[(((size_t)b * CK + ck) << 12) + p] = v;
}

// ---------------- kernel 3: deformable im2col ----------------
// grid (HW/256, 9, BATCH); each thread handles one (b,k,p), loops channels
__global__ void im2col_def(const float* __restrict__ x) {
    int p = blockIdx.x * blockDim.x + threadIdx.x;   // 0..4095
    int k = blockIdx.y;
    int b = blockIdx.z;
    int t = (k << 12) + p;
    int   i0 = g_gidx[t * 4 + 0], i1 = g_gidx[t * 4 + 1];
    int   i2 = g_gidx[t * 4 + 2], i3 = g_gidx[t * 4 + 3];
    float w0 = g_gw[t * 4 + 0], w1 = g_gw[t * 4 + 1];
    float w2 = g_gw[t * 4 + 2], w3 = g_gw[t * 4 + 3];
    const float* xb = x + (((size_t)b * CIN) << 12);
    float* out = g_bdef + (((size_t)b * CK + k) << 12) + p;
#pragma unroll 4
    for (int c = 0; c < CIN; c++) {
        const float* xc = xb + ((size_t)c << 12);
        float v = w0 * xc[i0] + w1 * xc[i1] + w2 * xc[i2] + w3 * xc[i3];
        out[(size_t)c * (9 * HW)] = v;   // K index = c*9 + k
    }
}

// ---------------- kernel 4: generic SGEMM ----------------
// C[b][m][n] (ldc=4096) = epilogue( sum_k A[m][k] * B[b][k][n] )
// epi=0: +bias[m];  epi=1: none;  epi=2: res[b][m][n] + scale[0]*acc
__global__ __launch_bounds__(256) void sgemm_kernel(
    const float* __restrict__ A, const float* __restrict__ B,
    float* __restrict__ C, const float* __restrict__ aux,
    const float* __restrict__ scalep,
    int M, int K,
    long long strideB, long long strideC, long long strideAux,
    int epi)
{
    const int N = NPIX;
    __shared__ float As[16][128];
    __shared__ float Bs[16][128];

    int tid = threadIdx.x;
    int tx = tid & 15;           // 0..15 -> col group
    int ty = tid >> 4;           // 0..15 -> row group
    int nbase = blockIdx.x * 128;
    int mbase = blockIdx.y * 128;
    int b     = blockIdx.z;

    const float* Bb = B + (long long)b * strideB;

    int arow  = tid >> 2;            // 0..63 (two passes cover 128 rows)
    int acol  = (tid & 3) << 2;      // 0,4,8,12
    int brow  = tid >> 4;            // 0..15
    int bcol  = (tid & 15) << 2;     // 0..60 (two passes: +0 and +64)

    float acc[8][8];
#pragma unroll
    for (int i = 0; i < 8; i++)
#pragma unroll
        for (int j = 0; j < 8; j++) acc[i][j] = 0.f;

    for (int k0 = 0; k0 < K; k0 += 16) {
        // load A tile (128 x 16), transposed into As[k][m]
#pragma unroll
        for (int pass = 0; pass < 2; pass++) {
            int r  = arow + pass * 64;
            int gm = mbase + r;
            float4 v = make_float4(0.f, 0.f, 0.f, 0.f);
            if (gm < M)
                v = *(const float4*)(A + (long long)gm * K + k0 + acol);
            As[acol + 0][r] = v.x;
            As[acol + 1][r] = v.y;
            As[acol + 2][r] = v.z;
            As[acol + 3][r] = v.w;
        }
        // load B tile (16 x 128)
#pragma unroll
        for (int pass = 0; pass < 2; pass++) {
            int cc = bcol + pass * 64;
            float4 v = *(const float4*)(Bb + (long long)(k0 + brow) * N + nbase + cc);
            *(float4*)&Bs[brow][cc] = v;
        }
        __syncthreads();

#pragma unroll
        for (int kk = 0; kk < 16; kk++) {
            float a[8], bb[8];
#pragma unroll
            for (int i = 0; i < 8; i++) a[i]  = As[kk][(ty << 3) + i];
#pragma unroll
            for (int j = 0; j < 8; j++) bb[j] = Bs[kk][(tx << 3) + j];
#pragma unroll
            for (int i = 0; i < 8; i++)
#pragma unroll
                for (int j = 0; j < 8; j++)
                    acc[i][j] += a[i] * bb[j];
        }
        __syncthreads();
    }

    float sc = (epi == 2) ? scalep[0] : 0.f;
#pragma unroll
    for (int i = 0; i < 8; i++) {
        int gm = mbase + (ty << 3) + i;
        if (gm >= M) continue;
        long long co = (long long)b * strideC + (long long)gm * N + nbase + (tx << 3);
        float out[8];
        if (epi == 0) {
            float bv = aux[gm];
#pragma unroll
            for (int j = 0; j < 8; j++) out[j] = acc[i][j] + bv;
        } else if (epi == 1) {
#pragma unroll
            for (int j = 0; j < 8; j++) out[j] = acc[i][j];
        } else {
            const float* res = aux + (long long)b * strideAux + (long long)gm * N + nbase + (tx << 3);
            float4 r0 = *(const float4*)(res + 0);
            float4 r1 = *(const float4*)(res + 4);
            out[0] = r0.x + sc * acc[i][0]; out[1] = r0.y + sc * acc[i][1];
            out[2] = r0.z + sc * acc[i][2]; out[3] = r0.w + sc * acc[i][3];
            out[4] = r1.x + sc * acc[i][4]; out[5] = r1.y + sc * acc[i][5];
            out[6] = r1.z + sc * acc[i][6]; out[7] = r1.w + sc * acc[i][7];
        }
        *(float4*)(C + co + 0) = make_float4(out[0], out[1], out[2], out[3]);
        *(float4*)(C + co + 4) = make_float4(out[4], out[5], out[6], out[7]);
    }
}

// ---------------- launch ----------------
extern "C" void kernel_launch(void* const* d_in, const int* in_sizes, int n_in,
                              void* d_out, int out_size) {
    const float* x      = (const float*)d_in[0];
    const float* weight = (const float*)d_in[1];   // [320,320,3,3] row-major => [o][c*9+k]
    const float* bias   = (const float*)d_in[2];
    const float* w_down = (const float*)d_in[3];   // [320,640]
    const float* w_up   = (const float*)d_in[4];   // [320,320]
    const float* scale  = (const float*)d_in[5];
    const float* offset = (const float*)d_in[6];   // [18,64,64]
    float* out = (float*)d_out;

    float* bconv; cudaGetSymbolAddress((void**)&bconv, g_bconv);
    float* bdef;  cudaGetSymbolAddress((void**)&bdef,  g_bdef);
    float* cat;   cudaGetSymbolAddress((void**)&cat,   g_cat);
    float* down;  cudaGetSymbolAddress((void**)&down,  g_down);

    // 1) gather precompute
    precompute_gather<<<(K9 * HW + 255) / 256, 256>>>(offset);

    // 2) im2col (conv patches + deformable patches)
    im2col_conv<<<dim3(HW / 256, CK, BATCH), 256>>>(x);
    im2col_def <<<dim3(HW / 256, K9, BATCH), 256>>>(x);

    dim3 grid(NPIX / 128, (COUT + 127) / 128, BATCH);

    // 3) h = W @ Bconv + bias  -> cat channels [320..639]
    sgemm_kernel<<<grid, 256>>>(weight, bconv,
                                cat + (long long)COUT * NPIX, bias, nullptr,
                                COUT, CK,
                                (long long)CK * NPIX, (long long)CAT2 * NPIX, 0, 0);

    // 4) dconv = W @ Bdef + bias -> cat channels [0..319]
    sgemm_kernel<<<grid, 256>>>(weight, bdef,
                                cat, bias, nullptr,
                                COUT, CK,
                                (long long)CK * NPIX, (long long)CAT2 * NPIX, 0, 0);

    // 5) down = w_down @ cat
    sgemm_kernel<<<grid, 256>>>(w_down, cat,
                                down, nullptr, nullptr,
                                COUT, CAT2,
                                (long long)CAT2 * NPIX, (long long)COUT * NPIX, 0, 1);

    // 6) out = h + scale * (w_up @ down)
    sgemm_kernel<<<grid, 256>>>(w_up, down,
                                out, cat + (long long)COUT * NPIX, scale,
                                COUT, COUT,
                                (long long)COUT * NPIX, (long long)COUT * NPIX,
                                (long long)CAT2 * NPIX, 2);
}

// round 2
// speedup vs baseline: 1.0013x; 1.0013x over previous
#include <cuda_runtime.h>

// ---------------- problem constants ----------------
#define BATCH 4
#define CIN   320
#define COUT  320
#define HH    64
#define WW    64
#define HW    4096           // 64*64
#define K9    9
#define CK    2880           // CIN*9
#define CAT2  640            // 2*COUT
#define NPIX  4096           // per-batch N

// ---------------- device scratch (static; no allocs) ----------------
__device__ float g_bconv[(size_t)BATCH * CK * HW];   // im2col of conv patches   (~189MB)
__device__ float g_bdef [(size_t)BATCH * CK * HW];   // im2col of deformable     (~189MB)
__device__ float g_cat  [(size_t)BATCH * CAT2 * HW]; // [dconv(0..319) ; h(320..639)]
__device__ float g_down [(size_t)BATCH * COUT * HW];
__device__ int   g_gidx [K9 * HW * 4];
__device__ float g_gw   [K9 * HW * 4];

// ---------------- kernel 1: gather precompute ----------------
__global__ void precompute_gather(const float* __restrict__ offset) {
    int t = blockIdx.x * blockDim.x + threadIdx.x;   // t = k*4096 + p
    if (t >= K9 * HW) return;
    int k = t >> 12;
    int p = t & 4095;
    int r = p >> 6, c = p & 63;
    float dy = offset[((k * 2 + 0) << 12) + p];
    float dx = offset[((k * 2 + 1) << 12) + p];
    float py = ((float)r - 1.0f + (float)(k / 3)) + dy;
    float px = ((float)c - 1.0f + (float)(k % 3)) + dx;
    float y0f = floorf(py), x0f = floorf(px);
    int y0 = (int)y0f, x0 = (int)x0f;
    float wy = py - y0f, wx = px - x0f;
    float ww[4] = { (1.f - wy) * (1.f - wx), (1.f - wy) * wx,
                    wy * (1.f - wx),         wy * wx };
#pragma unroll
    for (int j = 0; j < 4; j++) {
        int yy = y0 + (j >> 1);
        int xx = x0 + (j & 1);
        bool valid = (yy >= 0) && (yy < HH) && (xx >= 0) && (xx < WW);
        int yc = min(max(yy, 0), HH - 1);
        int xc = min(max(xx, 0), WW - 1);
        g_gidx[t * 4 + j] = yc * WW + xc;
        g_gw  [t * 4 + j] = valid ? ww[j] : 0.0f;
    }
}

// ---------------- kernel 2: conv im2col ----------------
// grid (HW/256, CK, BATCH)
__global__ void im2col_conv(const float* __restrict__ x) {
    int p  = blockIdx.x * blockDim.x + threadIdx.x;  // 0..4095
    int ck = blockIdx.y;
    int b  = blockIdx.z;
    int k = ck % 9, c = ck / 9;
    int r = (p >> 6) + k / 3 - 1;
    int q = (p & 63) + k % 3 - 1;
    float v = 0.f;
    if ((unsigned)r < (unsigned)HH && (unsigned)q < (unsigned)WW)
        v = x[(((size_t)b * CIN + c) << 12) + (r << 6) + q];
    g_bconv[(((size_t)b * CK + ck) << 12) + p] = v;
}

// ---------------- kernel 3: deformable im2col ----------------
// grid (HW/256, 9, BATCH); each thread handles one (b,k,p), loops channels
__global__ void im2col_def(const float* __restrict__ x) {
    int p = blockIdx.x * blockDim.x + threadIdx.x;   // 0..4095
    int k = blockIdx.y;
    int b = blockIdx.z;
    int t = (k << 12) + p;
    int   i0 = g_gidx[t * 4 + 0], i1 = g_gidx[t * 4 + 1];
    int   i2 = g_gidx[t * 4 + 2], i3 = g_gidx[t * 4 + 3];
    float w0 = g_gw[t * 4 + 0], w1 = g_gw[t * 4 + 1];
    float w2 = g_gw[t * 4 + 2], w3 = g_gw[t * 4 + 3];
    const float* xb = x + (((size_t)b * CIN) << 12);
    float* out = g_bdef + (((size_t)b * CK + k) << 12) + p;
#pragma unroll 4
    for (int c = 0; c < CIN; c++) {
        const float* xc = xb + ((size_t)c << 12);
        float v = w0 * xc[i0] + w1 * xc[i1] + w2 * xc[i2] + w3 * xc[i3];
        out[(size_t)c * (9 * HW)] = v;   // K index = c*9 + k
    }
}

// ---------------- kernel 4: generic SGEMM ----------------
// C[b][m][n] (ldc=4096) = epilogue( sum_k A[m][k] * B[b][k][n] )
// epi=0: +bias[m];  epi=1: none;  epi=2: res[b][m][n] + scale[0]*acc
__global__ __launch_bounds__(256) void sgemm_kernel(
    const float* __restrict__ A, const float* __restrict__ B,
    float* __restrict__ C, const float* __restrict__ aux,
    const float* __restrict__ scalep,
    int M, int K,
    long long strideB, long long strideC, long long strideAux,
    int epi)
{
    const int N = NPIX;
    __shared__ float As[16][128];
    __shared__ float Bs[16][128];

    int tid = threadIdx.x;
    int tx = tid & 15;           // 0..15 -> col group
    int ty = tid >> 4;           // 0..15 -> row group
    int nbase = blockIdx.x * 128;
    int mbase = blockIdx.y * 128;
    int b     = blockIdx.z;

    const float* Bb = B + (long long)b * strideB;

    int arow  = tid >> 2;            // 0..63 (two passes cover 128 rows)
    int acol  = (tid & 3) << 2;      // 0,4,8,12
    int brow  = tid >> 4;            // 0..15
    int bcol  = (tid & 15) << 2;     // 0..60 (two passes: +0 and +64)

    float acc[8][8];
#pragma unroll
    for (int i = 0; i < 8; i++)
#pragma unroll
        for (int j = 0; j < 8; j++) acc[i][j] = 0.f;

    for (int k0 = 0; k0 < K; k0 += 16) {
        // load A tile (128 x 16), transposed into As[k][m]
#pragma unroll
        for (int pass = 0; pass < 2; pass++) {
            int r  = arow + pass * 64;
            int gm = mbase + r;
            float4 v = make_float4(0.f, 0.f, 0.f, 0.f);
            if (gm < M)
                v = *(const float4*)(A + (long long)gm * K + k0 + acol);
            As[acol + 0][r] = v.x;
            As[acol + 1][r] = v.y;
            As[acol + 2][r] = v.z;
            As[acol + 3][r] = v.w;
        }
        // load B tile (16 x 128)
#pragma unroll
        for (int pass = 0; pass < 2; pass++) {
            int cc = bcol + pass * 64;
            float4 v = *(const float4*)(Bb + (long long)(k0 + brow) * N + nbase + cc);
            *(float4*)&Bs[brow][cc] = v;
        }
        __syncthreads();

#pragma unroll
        for (int kk = 0; kk < 16; kk++) {
            float a[8], bb[8];
#pragma unroll
            for (int i = 0; i < 8; i++) a[i]  = As[kk][(ty << 3) + i];
#pragma unroll
            for (int j = 0; j < 8; j++) bb[j] = Bs[kk][(tx << 3) + j];
#pragma unroll
            for (int i = 0; i < 8; i++)
#pragma unroll
                for (int j = 0; j < 8; j++)
                    acc[i][j] += a[i] * bb[j];
        }
        __syncthreads();
    }

    float sc = (epi == 2) ? scalep[0] : 0.f;
#pragma unroll
    for (int i = 0; i < 8; i++) {
        int gm = mbase + (ty << 3) + i;
        if (gm >= M) continue;
        long long co = (long long)b * strideC + (long long)gm * N + nbase + (tx << 3);
        float out[8];
        if (epi == 0) {
            float bv = aux[gm];
#pragma unroll
            for (int j = 0; j < 8; j++) out[j] = acc[i][j] + bv;
        } else if (epi == 1) {
#pragma unroll
            for (int j = 0; j < 8; j++) out[j] = acc[i][j];
        } else {
            const float* res = aux + (long long)b * strideAux + (long long)gm * N + nbase + (tx << 3);
            float4 r0 = *(const float4*)(res + 0);
            float4 r1 = *(const float4*)(res + 4);
            out[0] = r0.x + sc * acc[i][0]; out[1] = r0.y + sc * acc[i][1];
            out[2] = r0.z + sc * acc[i][2]; out[3] = r0.w + sc * acc[i][3];
            out[4] = r1.x + sc * acc[i][4]; out[5] = r1.y + sc * acc[i][5];
            out[6] = r1.z + sc * acc[i][6]; out[7] = r1.w + sc * acc[i][7];
        }
        *(float4*)(C + co + 0) = make_float4(out[0], out[1], out[2], out[3]);
        *(float4*)(C + co + 4) = make_float4(out[4], out[5], out[6], out[7]);
    }
}

// ---------------- launch ----------------
extern "C" void kernel_launch(void* const* d_in, const int* in_sizes, int n_in,
                              void* d_out, int out_size) {
    const float* x      = (const float*)d_in[0];
    const float* weight = (const float*)d_in[1];   // [320,320,3,3] row-major => [o][c*9+k]
    const float* bias   = (const float*)d_in[2];
    const float* w_down = (const float*)d_in[3];   // [320,640]
    const float* w_up   = (const float*)d_in[4];   // [320,320]
    const float* scale  = (const float*)d_in[5];
    const float* offset = (const float*)d_in[6];   // [18,64,64]
    float* out = (float*)d_out;

    float* bconv; cudaGetSymbolAddress((void**)&bconv, g_bconv);
    float* bdef;  cudaGetSymbolAddress((void**)&bdef,  g_bdef);
    float* cat;   cudaGetSymbolAddress((void**)&cat,   g_cat);
    float* down;  cudaGetSymbolAddress((void**)&down,  g_down);

    // 1) gather precompute
    precompute_gather<<<(K9 * HW + 255) / 256, 256>>>(offset);

    // 2) im2col (conv patches + deformable patches)
    im2col_conv<<<dim3(HW / 256, CK, BATCH), 256>>>(x);
    im2col_def <<<dim3(HW / 256, K9, BATCH), 256>>>(x);

    dim3 grid(NPIX / 128, (COUT + 127) / 128, BATCH);

    // 3) h = W @ Bconv + bias  -> cat channels [320..639]
    sgemm_kernel<<<grid, 256>>>(weight, bconv,
                                cat + (long long)COUT * NPIX, bias, nullptr,
                                COUT, CK,
                                (long long)CK * NPIX, (long long)CAT2 * NPIX, 0, 0);

    // 4) dconv = W @ Bdef + bias -> cat channels [0..319]
    sgemm_kernel<<<grid, 256>>>(weight, bdef,
                                cat, bias, nullptr,
                                COUT, CK,
                                (long long)CK * NPIX, (long long)CAT2 * NPIX, 0, 0);

    // 5) down = w_down @ cat
    sgemm_kernel<<<grid, 256>>>(w_down, cat,
                                down, nullptr, nullptr,
                                COUT, CAT2,
                                (long long)CAT2 * NPIX, (long long)COUT * NPIX, 0, 1);

    // 6) out = h + scale * (w_up @ down)
    sgemm_kernel<<<grid, 256>>>(w_up, down,
                                out, cat + (long long)COUT * NPIX, scale,
                                COUT, COUT,
                                (long long)COUT * NPIX, (long long)COUT * NPIX,
                                (long long)CAT2 * NPIX, 2);
}

// round 4
// speedup vs baseline: 2.2625x; 2.2595x over previous
#include <cuda_runtime.h>
#include <cuda_bf16.h>
#include <cstdint>

#define BATCH 4
#define CIN   320
#define COUT  320
#define HW    4096
#define CK    2880           // K = c*9 + k (native weight layout)
#define CAT2  640
#define STGB  30720          // bytes per pipeline stage
#define SMEMB (2 * STGB)     // 61440

// ---------------- device scratch ----------------
__device__ __nv_bfloat16 g_Ach[(size_t)BATCH*HW*CK], g_Acl[(size_t)BATCH*HW*CK];
__device__ __nv_bfloat16 g_Adh[(size_t)BATCH*HW*CK], g_Adl[(size_t)BATCH*HW*CK];
__device__ __nv_bfloat16 g_wth[COUT*CK],   g_wtl[COUT*CK];
__device__ __nv_bfloat16 g_wdh[COUT*CAT2], g_wdl[COUT*CAT2];
__device__ __nv_bfloat16 g_wuh[COUT*COUT], g_wul[COUT*COUT];
__device__ __nv_bfloat16 g_cth[(size_t)BATCH*HW*CAT2], g_ctl[(size_t)BATCH*HW*CAT2];
__device__ __nv_bfloat16 g_dnh[(size_t)BATCH*HW*COUT], g_dnl[(size_t)BATCH*HW*COUT];
__device__ float  g_hF[(size_t)BATCH*COUT*HW];
__device__ int    g_ci[9*HW];
__device__ float  g_cw[9*HW];
__device__ int4   g_idf[9*HW];
__device__ float4 g_wdf[9*HW];

// ---------------- helpers ----------------
__device__ __forceinline__ uint32_t smem_u32(const void* p) {
    uint32_t a;
    asm("{ .reg .u64 t; cvta.to.shared.u64 t, %1; cvt.u32.u64 %0, t; }" : "=r"(a) : "l"(p));
    return a;
}
__device__ __forceinline__ void cpa16(uint32_t dst, const void* src) {
    asm volatile("cp.async.cg.shared.global [%0], [%1], 16;" :: "r"(dst), "l"(src));
}
#define LDM4(r, addr) \
    asm volatile("ldmatrix.sync.aligned.m8n8.x4.shared.b16 {%0,%1,%2,%3}, [%4];" \
        : "=r"((r)[0]), "=r"((r)[1]), "=r"((r)[2]), "=r"((r)[3]) : "r"(addr))
#define MMA_BF16(c, a, bq) \
    asm volatile("mma.sync.aligned.m16n8k16.row.col.f32.bf16.bf16.f32 " \
        "{%0,%1,%2,%3}, {%4,%5,%6,%7}, {%8,%9}, {%0,%1,%2,%3};" \
        : "+f"((c)[0]), "+f"((c)[1]), "+f"((c)[2]), "+f"((c)[3]) \
        : "r"((a)[0]), "r"((a)[1]), "r"((a)[2]), "r"((a)[3]), "r"((bq)[0]), "r"((bq)[1]))

__device__ __forceinline__ void bsplit(float v, __nv_bfloat16& h, __nv_bfloat16& l) {
    h = __float2bfloat16(v);
    l = __float2bfloat16(v - __bfloat162float(h));
}
__device__ __forceinline__ uint32_t bpack(__nv_bfloat16 a, __nv_bfloat16 b) {
    return (uint32_t)__bfloat16_as_ushort(a) | ((uint32_t)__bfloat16_as_ushort(b) << 16);
}

// ---------------- table precompute ----------------
__global__ void precompute(const float* __restrict__ off) {
    int t = blockIdx.x * 256 + threadIdx.x;
    if (t >= 9 * HW) return;
    int k = t >> 12, p = t & 4095;
    int r = p >> 6, c = p & 63;
    int rr = r + k / 3 - 1, qq = c + k % 3 - 1;
    bool vb = (rr >= 0 && rr < 64 && qq >= 0 && qq < 64);
    g_ci[t] = vb ? rr * 64 + qq : 0;
    g_cw[t] = vb ? 1.f : 0.f;
    float dy = off[((k*2+0) << 12) + p];
    float dx = off[((k*2+1) << 12) + p];
    float py = (float)rr + dy, px = (float)qq + dx;
    float y0f = floorf(py), x0f = floorf(px);
    int y0 = (int)y0f, x0 = (int)x0f;
    float wy = py - y0f, wx = px - x0f;
    float wv[4] = { (1.f-wy)*(1.f-wx), (1.f-wy)*wx, wy*(1.f-wx), wy*wx };
    int   idx[4]; float wgt[4];
#pragma unroll
    for (int j = 0; j < 4; j++) {
        int yy = y0 + (j >> 1), xx = x0 + (j & 1);
        bool ok = (yy >= 0 && yy < 64 && xx >= 0 && xx < 64);
        idx[j] = (min(max(yy,0),63) << 6) + min(max(xx,0),63);
        wgt[j] = ok ? wv[j] : 0.f;
    }
    g_idf[t] = make_int4(idx[0], idx[1], idx[2], idx[3]);
    g_wdf[t] = make_float4(wgt[0], wgt[1], wgt[2], wgt[3]);
}

__global__ void split_plain(const float* __restrict__ s, __nv_bfloat16* hi, __nv_bfloat16* lo, int n) {
    int i = blockIdx.x * 256 + threadIdx.x;
    if (i >= n) return;
    __nv_bfloat16 h, l; bsplit(s[i], h, l);
    hi[i] = h; lo[i] = l;
}

// ---------------- fused im2col (conv + deformable), K = c*9+k ----------------
__device__ __forceinline__ void store72(__nv_bfloat16* __restrict__ H,
                                        __nv_bfloat16* __restrict__ L,
                                        const float* tv) {
#pragma unroll
    for (int q = 0; q < 9; q++) {
        uint32_t hh[4], ll[4];
#pragma unroll
        for (int m = 0; m < 4; m++) {
            __nv_bfloat16 h0, l0, h1, l1;
            bsplit(tv[q*8 + 2*m],     h0, l0);
            bsplit(tv[q*8 + 2*m + 1], h1, l1);
            hh[m] = bpack(h0, h1); ll[m] = bpack(l0, l1);
        }
        ((uint4*)H)[q] = make_uint4(hh[0], hh[1], hh[2], hh[3]);
        ((uint4*)L)[q] = make_uint4(ll[0], ll[1], ll[2], ll[3]);
    }
}

__global__ __launch_bounds__(256) void im2col_fused(
    const float* __restrict__ x,
    __nv_bfloat16* __restrict__ Ach, __nv_bfloat16* __restrict__ Acl,
    __nv_bfloat16* __restrict__ Adh, __nv_bfloat16* __restrict__ Adl)
{
    extern __shared__ float pl[];   // 8 channel planes, 8*4096 f32 = 128KB
    int b  = blockIdx.y;
    int c0 = blockIdx.x * 8;
    for (int idx = threadIdx.x; idx < 8 * 4096; idx += 256)
        pl[idx] = x[(((size_t)b * CIN + c0) << 12) + idx];
    __syncthreads();

    for (int p = threadIdx.x; p < 4096; p += 256) {
        float tv[72];
        size_t o = ((size_t)(b * HW) + p) * CK + (size_t)c0 * 9;
        // conv taps (single tap, weight 0/1)
#pragma unroll
        for (int k = 0; k < 9; k++) {
            int   ci = g_ci[(k << 12) + p];
            float cw = g_cw[(k << 12) + p];
#pragma unroll
            for (int c = 0; c < 8; c++)
                tv[c*9 + k] = cw * pl[(c << 12) + ci];
        }
        store72(Ach + o, Acl + o, tv);
        // deformable taps (bilinear)
#pragma unroll
        for (int k = 0; k < 9; k++) {
            int4   di = g_idf[(k << 12) + p];
            float4 dw = g_wdf[(k << 12) + p];
#pragma unroll
            for (int c = 0; c < 8; c++) {
                const float* q = pl + (c << 12);
                tv[c*9 + k] = dw.x*q[di.x] + dw.y*q[di.y] + dw.z*q[di.z] + dw.w*q[di.w];
            }
        }
        store72(Adh + o, Adl + o, tv);
    }
}

// ---------------- HMMA GEMM: D[128 pix][64 ch] = sum_K A[pix][K]*B[ch][K], bf16x3 ----------------
// MODE 0: +bias -> hF (f32 ch-major) and cat hi/lo @cofs
// MODE 1: +bias -> cat hi/lo @cofs
// MODE 2: -> dn hi/lo
// MODE 3: out = hF + scale*acc (f32 ch-major)
template<int MODE>
__global__ void __launch_bounds__(256) gemm_mma(
    const __nv_bfloat16* __restrict__ Ah, const __nv_bfloat16* __restrict__ Al,
    const __nv_bfloat16* __restrict__ Bh, const __nv_bfloat16* __restrict__ Bl,
    int K, const float* __restrict__ bias, float* __restrict__ hF,
    __nv_bfloat16* __restrict__ Oh, __nv_bfloat16* __restrict__ Ol, int ldo, int cofs,
    float* __restrict__ out, const float* __restrict__ scalep)
{
    extern __shared__ char smem[];
    uint32_t sb = smem_u32(smem);
    float* fst = (float*)smem;                  // epilogue stage [64][132]
    int tid = threadIdx.x;
    int b = blockIdx.z;
    int pix0 = blockIdx.x * 128;
    int ch0  = blockIdx.y * 64;
    int NCH = K >> 5;

    const __nv_bfloat16* Abh = Ah + (size_t)(b * HW + pix0) * K;
    const __nv_bfloat16* Abl = Al + (size_t)(b * HW + pix0) * K;
    const __nv_bfloat16* Bbh = Bh + (size_t)ch0 * K;
    const __nv_bfloat16* Bbl = Bl + (size_t)ch0 * K;

    int w = tid >> 5, lane = tid & 31;
    int m0 = (w & 3) * 32, n0 = (w >> 2) * 32;
    int a_r = (lane & 7) + ((lane >> 3) & 1) * 8;
    int a_c = ((lane >> 4) & 1) * 16;
    int b_r = (lane & 7) + ((lane >> 4) & 1) * 8;
    int b_c = ((lane >> 3) & 1) * 16;

    float acc[2][4][4];
#pragma unroll
    for (int i = 0; i < 2; i++)
#pragma unroll
        for (int j = 0; j < 4; j++)
#pragma unroll
            for (int q = 0; q < 4; q++) acc[i][j][q] = 0.f;

    auto load_stage = [&](int ci) {
        uint32_t st = sb + (uint32_t)(ci & 1) * STGB;
        int k0 = ci << 5;
#pragma unroll
        for (int it = 0; it < 2; it++) {        // A: 128 rows x 64B (hi & lo)
            int idx = tid + it * 256;
            int r = idx >> 2, j = idx & 3;
            cpa16(st +         r * 80 + j * 16, Abh + (size_t)r * K + k0 + j * 8);
            cpa16(st + 10240 + r * 80 + j * 16, Abl + (size_t)r * K + k0 + j * 8);
        }
        {                                        // B: 64 rows x 64B (hi & lo)
            int r = tid >> 2, j = tid & 3;
            cpa16(st + 20480 + r * 80 + j * 16, Bbh + (size_t)r * K + k0 + j * 8);
            cpa16(st + 25600 + r * 80 + j * 16, Bbl + (size_t)r * K + k0 + j * 8);
        }
        asm volatile("cp.async.commit_group;" ::: "memory");
    };

    load_stage(0);
    for (int i = 0; i < NCH; i++) {
        if (i + 1 < NCH) {
            load_stage(i + 1);
            asm volatile("cp.async.wait_group 1;" ::: "memory");
        } else {
            asm volatile("cp.async.wait_group 0;" ::: "memory");
        }
        __syncthreads();
        uint32_t st = sb + (uint32_t)(i & 1) * STGB;
#pragma unroll
        for (int kk = 0; kk < 2; kk++) {
            uint32_t ah[2][4], al[2][4];
#pragma unroll
            for (int mf = 0; mf < 2; mf++) {
                uint32_t ad = st + (uint32_t)(m0 + mf * 16 + a_r) * 80 + kk * 32 + a_c;
                LDM4(ah[mf], ad);
                LDM4(al[mf], ad + 10240);
            }
#pragma unroll
            for (int np = 0; np < 2; np++) {
                uint32_t bh[4], bl[4];
                uint32_t bd = st + 20480 + (uint32_t)(n0 + np * 16 + b_r) * 80 + kk * 32 + b_c;
                LDM4(bh, bd);
                LDM4(bl, bd + 5120);
#pragma unroll
                for (int mf = 0; mf < 2; mf++)
#pragma unroll
                    for (int h = 0; h < 2; h++) {
                        float* c = acc[mf][np * 2 + h];
                        MMA_BF16(c, ah[mf], bh + 2 * h);
                        MMA_BF16(c, ah[mf], bl + 2 * h);
                        MMA_BF16(c, al[mf], bh + 2 * h);
                    }
            }
        }
        __syncthreads();
    }

    // ---- epilogue: stage acc into smem [ch 64][pix 132] ----
#pragma unroll
    for (int mf = 0; mf < 2; mf++)
#pragma unroll
        for (int nf = 0; nf < 4; nf++) {
            int pr = m0 + mf * 16 + (lane >> 2);
            int nc = n0 + nf * 8 + 2 * (lane & 3);
            fst[nc * 132 + pr]            = acc[mf][nf][0];
            fst[(nc + 1) * 132 + pr]      = acc[mf][nf][1];
            fst[nc * 132 + pr + 8]        = acc[mf][nf][2];
            fst[(nc + 1) * 132 + pr + 8]  = acc[mf][nf][3];
        }
    __syncthreads();

    if (MODE == 0 || MODE == 3) {
        float sc = (MODE == 3) ? *scalep : 0.f;
        for (int idx = tid; idx < 8192; idx += 256) {
            int n = idx >> 7, p = idx & 127;
            float v = fst[n * 132 + p];
            size_t o = (((size_t)b * COUT + ch0 + n) << 12) + pix0 + p;
            if (MODE == 0) hF[o] = v + __ldg(bias + ch0 + n);
            else           out[o] = hF[o] + sc * v;
        }
    }
    if (MODE <= 2) {
        int p = tid >> 1, hf2 = tid & 1;
        size_t row = ((size_t)(b * HW) + pix0 + p) * ldo + cofs + ch0 + hf2 * 32;
        uint32_t uh[16], ul[16];
#pragma unroll
        for (int m = 0; m < 16; m++) {
            int n = hf2 * 32 + 2 * m;
            float v0 = fst[n * 132 + p], v1 = fst[(n + 1) * 132 + p];
            if (MODE <= 1) {
                v0 += __ldg(bias + ch0 + n);
                v1 += __ldg(bias + ch0 + n + 1);
            }
            __nv_bfloat16 h0, l0, h1, l1;
            bsplit(v0, h0, l0); bsplit(v1, h1, l1);
            uh[m] = bpack(h0, h1); ul[m] = bpack(l0, l1);
        }
#pragma unroll
        for (int q = 0; q < 4; q++) {
            ((uint4*)(Oh + row))[q] = make_uint4(uh[4*q], uh[4*q+1], uh[4*q+2], uh[4*q+3]);
            ((uint4*)(Ol + row))[q] = make_uint4(ul[4*q], ul[4*q+1], ul[4*q+2], ul[4*q+3]);
        }
    }
}

// ---------------- launch ----------------
extern "C" void kernel_launch(void* const* d_in, const int* in_sizes, int n_in,
                              void* d_out, int out_size) {
    const float* x      = (const float*)d_in[0];
    const float* weight = (const float*)d_in[1];
    const float* bias   = (const float*)d_in[2];
    const float* w_down = (const float*)d_in[3];
    const float* w_up   = (const float*)d_in[4];
    const float* scale  = (const float*)d_in[5];
    const float* offset = (const float*)d_in[6];
    float* out = (float*)d_out;

    __nv_bfloat16 *Ach, *Acl, *Adh, *Adl, *wth, *wtl, *wdh, *wdl, *wuh, *wul, *cth, *ctl, *dnh, *dnl;
    float *hF;
    cudaGetSymbolAddress((void**)&Ach, g_Ach); cudaGetSymbolAddress((void**)&Acl, g_Acl);
    cudaGetSymbolAddress((void**)&Adh, g_Adh); cudaGetSymbolAddress((void**)&Adl, g_Adl);
    cudaGetSymbolAddress((void**)&wth, g_wth); cudaGetSymbolAddress((void**)&wtl, g_wtl);
    cudaGetSymbolAddress((void**)&wdh, g_wdh); cudaGetSymbolAddress((void**)&wdl, g_wdl);
    cudaGetSymbolAddress((void**)&wuh, g_wuh); cudaGetSymbolAddress((void**)&wul, g_wul);
    cudaGetSymbolAddress((void**)&cth, g_cth); cudaGetSymbolAddress((void**)&ctl, g_ctl);
    cudaGetSymbolAddress((void**)&dnh, g_dnh); cudaGetSymbolAddress((void**)&dnl, g_dnl);
    cudaGetSymbolAddress((void**)&hF,  g_hF);

    cudaFuncSetAttribute(im2col_fused, cudaFuncAttributeMaxDynamicSharedMemorySize, 131072);
    cudaFuncSetAttribute(gemm_mma<0>, cudaFuncAttributeMaxDynamicSharedMemorySize, SMEMB);
    cudaFuncSetAttribute(gemm_mma<1>, cudaFuncAttributeMaxDynamicSharedMemorySize, SMEMB);
    cudaFuncSetAttribute(gemm_mma<2>, cudaFuncAttributeMaxDynamicSharedMemorySize, SMEMB);
    cudaFuncSetAttribute(gemm_mma<3>, cudaFuncAttributeMaxDynamicSharedMemorySize, SMEMB);

    precompute<<<(9 * HW + 255) / 256, 256>>>(offset);
    split_plain<<<(COUT * CK   + 255) / 256, 256>>>(weight, wth, wtl, COUT * CK);
    split_plain<<<(COUT * CAT2 + 255) / 256, 256>>>(w_down, wdh, wdl, COUT * CAT2);
    split_plain<<<(COUT * COUT + 255) / 256, 256>>>(w_up,   wuh, wul, COUT * COUT);

    im2col_fused<<<dim3(40, BATCH), 256, 131072>>>(x, Ach, Acl, Adh, Adl);

    dim3 grid(HW / 128, COUT / 64, BATCH);
    // h = conv + bias -> hF, cat[:, 320:640]
    gemm_mma<0><<<grid, 256, SMEMB>>>(Ach, Acl, wth, wtl, CK, bias, hF,
                                      cth, ctl, CAT2, COUT, nullptr, nullptr);
    // dconv + bias -> cat[:, 0:320]
    gemm_mma<1><<<grid, 256, SMEMB>>>(Adh, Adl, wth, wtl, CK, bias, nullptr,
                                      cth, ctl, CAT2, 0, nullptr, nullptr);
    // down = w_down @ cat -> dn
    gemm_mma<2><<<grid, 256, SMEMB>>>(cth, ctl, wdh, wdl, CAT2, nullptr, nullptr,
                                      dnh, dnl, COUT, 0, nullptr, nullptr);
    // out = hF + scale * (w_up @ dn)
    gemm_mma<3><<<grid, 256, SMEMB>>>(dnh, dnl, wuh, wul, COUT, nullptr, hF,
                                      nullptr, nullptr, 0, 0, out, scale);
}

// round 5
// speedup vs baseline: 2.3695x; 1.0473x over previous
#include <cuda_runtime.h>
#include <cuda_bf16.h>
#include <cstdint>

#define BATCH 4
#define CIN   320
#define COUT  320
#define HW    4096
#define CK    2880           // K = c*9 + k (native weight layout)
#define CAT2  640
// stage: A 128x80B x2 (hi,lo) = 20480 ; B 320x80B x2 = 51200 ; total 71680
#define STGB  71680
#define SMEMB (2 * STGB)     // 143360

// ---------------- device scratch ----------------
__device__ __nv_bfloat16 g_Ach[(size_t)BATCH*HW*CK], g_Acl[(size_t)BATCH*HW*CK];
__device__ __nv_bfloat16 g_Adh[(size_t)BATCH*HW*CK], g_Adl[(size_t)BATCH*HW*CK];
__device__ __nv_bfloat16 g_wth[COUT*CK],   g_wtl[COUT*CK];
__device__ __nv_bfloat16 g_wdh[COUT*CAT2], g_wdl[COUT*CAT2];
__device__ __nv_bfloat16 g_wuh[COUT*COUT], g_wul[COUT*COUT];
__device__ __nv_bfloat16 g_cth[(size_t)BATCH*HW*CAT2], g_ctl[(size_t)BATCH*HW*CAT2];
__device__ __nv_bfloat16 g_dnh[(size_t)BATCH*HW*COUT], g_dnl[(size_t)BATCH*HW*COUT];
__device__ float  g_hF[(size_t)BATCH*COUT*HW];
__device__ int    g_ci[9*HW];
__device__ float  g_cw[9*HW];
__device__ int4   g_idf[9*HW];
__device__ float4 g_wdf[9*HW];

// ---------------- helpers ----------------
__device__ __forceinline__ uint32_t smem_u32(const void* p) {
    uint32_t a;
    asm("{ .reg .u64 t; cvta.to.shared.u64 t, %1; cvt.u32.u64 %0, t; }" : "=r"(a) : "l"(p));
    return a;
}
__device__ __forceinline__ void cpa16(uint32_t dst, const void* src) {
    asm volatile("cp.async.cg.shared.global [%0], [%1], 16;" :: "r"(dst), "l"(src));
}
#define LDM4(r, addr) \
    asm volatile("ldmatrix.sync.aligned.m8n8.x4.shared.b16 {%0,%1,%2,%3}, [%4];" \
        : "=r"((r)[0]), "=r"((r)[1]), "=r"((r)[2]), "=r"((r)[3]) : "r"(addr))
#define MMA_BF16(c, a, bq) \
    asm volatile("mma.sync.aligned.m16n8k16.row.col.f32.bf16.bf16.f32 " \
        "{%0,%1,%2,%3}, {%4,%5,%6,%7}, {%8,%9}, {%0,%1,%2,%3};" \
        : "+f"((c)[0]), "+f"((c)[1]), "+f"((c)[2]), "+f"((c)[3]) \
        : "r"((a)[0]), "r"((a)[1]), "r"((a)[2]), "r"((a)[3]), "r"((bq)[0]), "r"((bq)[1]))

__device__ __forceinline__ void bsplit(float v, __nv_bfloat16& h, __nv_bfloat16& l) {
    h = __float2bfloat16(v);
    l = __float2bfloat16(v - __bfloat162float(h));
}
__device__ __forceinline__ uint32_t bpack(__nv_bfloat16 a, __nv_bfloat16 b) {
    return (uint32_t)__bfloat16_as_ushort(a) | ((uint32_t)__bfloat16_as_ushort(b) << 16);
}

// ---------------- table precompute ----------------
__global__ void precompute(const float* __restrict__ off) {
    int t = blockIdx.x * 256 + threadIdx.x;
    if (t >= 9 * HW) return;
    int k = t >> 12, p = t & 4095;
    int r = p >> 6, c = p & 63;
    int rr = r + k / 3 - 1, qq = c + k % 3 - 1;
    bool vb = (rr >= 0 && rr < 64 && qq >= 0 && qq < 64);
    g_ci[t] = vb ? rr * 64 + qq : 0;
    g_cw[t] = vb ? 1.f : 0.f;
    float dy = off[((k*2+0) << 12) + p];
    float dx = off[((k*2+1) << 12) + p];
    float py = (float)rr + dy, px = (float)qq + dx;
    float y0f = floorf(py), x0f = floorf(px);
    int y0 = (int)y0f, x0 = (int)x0f;
    float wy = py - y0f, wx = px - x0f;
    float wv[4] = { (1.f-wy)*(1.f-wx), (1.f-wy)*wx, wy*(1.f-wx), wy*wx };
    int   idx[4]; float wgt[4];
#pragma unroll
    for (int j = 0; j < 4; j++) {
        int yy = y0 + (j >> 1), xx = x0 + (j & 1);
        bool ok = (yy >= 0 && yy < 64 && xx >= 0 && xx < 64);
        idx[j] = (min(max(yy,0),63) << 6) + min(max(xx,0),63);
        wgt[j] = ok ? wv[j] : 0.f;
    }
    g_idf[t] = make_int4(idx[0], idx[1], idx[2], idx[3]);
    g_wdf[t] = make_float4(wgt[0], wgt[1], wgt[2], wgt[3]);
}

__global__ void split_plain(const float* __restrict__ s, __nv_bfloat16* hi, __nv_bfloat16* lo, int n) {
    int i = blockIdx.x * 256 + threadIdx.x;
    if (i >= n) return;
    __nv_bfloat16 h, l; bsplit(s[i], h, l);
    hi[i] = h; lo[i] = l;
}

// ---------------- fused im2col (conv + deformable), K = c*9+k ----------------
__device__ __forceinline__ void store72(__nv_bfloat16* __restrict__ H,
                                        __nv_bfloat16* __restrict__ L,
                                        const float* tv) {
#pragma unroll
    for (int q = 0; q < 9; q++) {
        uint32_t hh[4], ll[4];
#pragma unroll
        for (int m = 0; m < 4; m++) {
            __nv_bfloat16 h0, l0, h1, l1;
            bsplit(tv[q*8 + 2*m],     h0, l0);
            bsplit(tv[q*8 + 2*m + 1], h1, l1);
            hh[m] = bpack(h0, h1); ll[m] = bpack(l0, l1);
        }
        ((uint4*)H)[q] = make_uint4(hh[0], hh[1], hh[2], hh[3]);
        ((uint4*)L)[q] = make_uint4(ll[0], ll[1], ll[2], ll[3]);
    }
}

__global__ __launch_bounds__(256) void im2col_fused(
    const float* __restrict__ x,
    __nv_bfloat16* __restrict__ Ach, __nv_bfloat16* __restrict__ Acl,
    __nv_bfloat16* __restrict__ Adh, __nv_bfloat16* __restrict__ Adl)
{
    extern __shared__ float pl[];   // 8 channel planes = 128KB
    int b  = blockIdx.y;
    int c0 = blockIdx.x * 8;
    for (int idx = threadIdx.x; idx < 8 * 4096; idx += 256)
        pl[idx] = x[(((size_t)b * CIN + c0) << 12) + idx];
    __syncthreads();

    for (int p = threadIdx.x; p < 4096; p += 256) {
        float tv[72];
        size_t o = ((size_t)(b * HW) + p) * CK + (size_t)c0 * 9;
#pragma unroll
        for (int k = 0; k < 9; k++) {
            int   ci = g_ci[(k << 12) + p];
            float cw = g_cw[(k << 12) + p];
#pragma unroll
            for (int c = 0; c < 8; c++)
                tv[c*9 + k] = cw * pl[(c << 12) + ci];
        }
        store72(Ach + o, Acl + o, tv);
#pragma unroll
        for (int k = 0; k < 9; k++) {
            int4   di = g_idf[(k << 12) + p];
            float4 dw = g_wdf[(k << 12) + p];
#pragma unroll
            for (int c = 0; c < 8; c++) {
                const float* q = pl + (c << 12);
                tv[c*9 + k] = dw.x*q[di.x] + dw.y*q[di.y] + dw.z*q[di.z] + dw.w*q[di.w];
            }
        }
        store72(Adh + o, Adl + o, tv);
    }
}

// ---------------- HMMA GEMM: D[128 pix][320 ch] = sum_K A[pix][K]*B[ch][K], bf16x3 ----------------
// MODE 0 (big dual): grid.y=0 -> A=def, cat[:,0:320]; grid.y=1 -> A=conv, cat[:,320:640] + hF. +bias.
// MODE 1 (down): A=cat (K=640), out dn hi/lo.
// MODE 2 (up):   A=dn (K=320), out = hF + scale*acc (f32 ch-major).
template<int MODE>
__global__ void __launch_bounds__(256, 1) gemm_mma(
    const __nv_bfloat16* __restrict__ Ah0, const __nv_bfloat16* __restrict__ Al0,
    const __nv_bfloat16* __restrict__ Ah1, const __nv_bfloat16* __restrict__ Al1,
    const __nv_bfloat16* __restrict__ Bh, const __nv_bfloat16* __restrict__ Bl,
    int K, const float* __restrict__ bias, float* __restrict__ hF,
    __nv_bfloat16* __restrict__ Oh, __nv_bfloat16* __restrict__ Ol, int ldo,
    float* __restrict__ out, const float* __restrict__ scalep)
{
    extern __shared__ char smem[];
    uint32_t sb = smem_u32(smem);
    float* fst = (float*)smem;                  // epilogue stage [160][132]
    int tid = threadIdx.x;
    int b = blockIdx.z;
    int pix0 = blockIdx.x * 128;
    int yy = (MODE == 0) ? blockIdx.y : 0;
    int NCH = K >> 5;

    const __nv_bfloat16* Abh = ((MODE == 0 && yy == 1) ? Ah1 : Ah0) + (size_t)(b * HW + pix0) * K;
    const __nv_bfloat16* Abl = ((MODE == 0 && yy == 1) ? Al1 : Al0) + (size_t)(b * HW + pix0) * K;
    int cofs = (MODE == 0 && yy == 1) ? 320 : 0;

    int w = tid >> 5, lane = tid & 31;
    int m0 = (w & 3) * 32;
    int ng = w >> 2;                  // 0 or 1: channel group base ng*160
    int a_r = (lane & 7) + ((lane >> 3) & 1) * 8;
    int a_c = ((lane >> 4) & 1) * 16;
    int b_r = (lane & 7) + ((lane >> 4) & 1) * 8;
    int b_c = ((lane >> 3) & 1) * 16;

    float acc[2][20][4];
#pragma unroll
    for (int i = 0; i < 2; i++)
#pragma unroll
        for (int j = 0; j < 20; j++)
#pragma unroll
            for (int q = 0; q < 4; q++) acc[i][j][q] = 0.f;

    auto load_stage = [&](int ci) {
        uint32_t st = sb + (uint32_t)(ci & 1) * STGB;
        int k0 = ci << 5;
#pragma unroll
        for (int it = 0; it < 2; it++) {        // A: 128 rows x 64B (hi & lo)
            int idx = tid + it * 256;
            int r = idx >> 2, j = idx & 3;
            cpa16(st +         r * 80 + j * 16, Abh + (size_t)r * K + k0 + j * 8);
            cpa16(st + 10240 + r * 80 + j * 16, Abl + (size_t)r * K + k0 + j * 8);
        }
#pragma unroll
        for (int it = 0; it < 5; it++) {        // B: 320 rows x 64B (hi & lo)
            int idx = tid + it * 256;
            int r = idx >> 2, j = idx & 3;
            cpa16(st + 20480 + r * 80 + j * 16, Bh + (size_t)r * K + k0 + j * 8);
            cpa16(st + 46080 + r * 80 + j * 16, Bl + (size_t)r * K + k0 + j * 8);
        }
        asm volatile("cp.async.commit_group;" ::: "memory");
    };

    load_stage(0);
    for (int i = 0; i < NCH; i++) {
        if (i + 1 < NCH) {
            load_stage(i + 1);
            asm volatile("cp.async.wait_group 1;" ::: "memory");
        } else {
            asm volatile("cp.async.wait_group 0;" ::: "memory");
        }
        __syncthreads();
        uint32_t st = sb + (uint32_t)(i & 1) * STGB;
#pragma unroll
        for (int kk = 0; kk < 2; kk++) {
            uint32_t ah[2][4], al[2][4];
#pragma unroll
            for (int mf = 0; mf < 2; mf++) {
                uint32_t ad = st + (uint32_t)(m0 + mf * 16 + a_r) * 80 + kk * 32 + a_c;
                LDM4(ah[mf], ad);
                LDM4(al[mf], ad + 10240);
            }
#pragma unroll
            for (int np = 0; np < 10; np++) {
                uint32_t bh[4], bl[4];
                uint32_t bd = st + 20480 + (uint32_t)(ng * 160 + np * 16 + b_r) * 80 + kk * 32 + b_c;
                LDM4(bh, bd);
                LDM4(bl, bd + 25600);
#pragma unroll
                for (int mf = 0; mf < 2; mf++)
#pragma unroll
                    for (int h = 0; h < 2; h++) {
                        float* c = acc[mf][np * 2 + h];
                        MMA_BF16(c, ah[mf], bh + 2 * h);
                        MMA_BF16(c, ah[mf], bl + 2 * h);
                        MMA_BF16(c, al[mf], bh + 2 * h);
                    }
            }
        }
        __syncthreads();
    }

    // ---- epilogue: 2 chunks of 160 channels staged via smem [160][132] ----
    float sc = (MODE == 2) ? *scalep : 0.f;
    for (int g = 0; g < 2; g++) {
        if (ng == g) {
#pragma unroll
            for (int mf = 0; mf < 2; mf++)
#pragma unroll
                for (int nf = 0; nf < 20; nf++) {
                    int pr = m0 + mf * 16 + (lane >> 2);
                    int nc = nf * 8 + 2 * (lane & 3);
                    fst[nc * 132 + pr]           = acc[mf][nf][0];
                    fst[(nc + 1) * 132 + pr]     = acc[mf][nf][1];
                    fst[nc * 132 + pr + 8]       = acc[mf][nf][2];
                    fst[(nc + 1) * 132 + pr + 8] = acc[mf][nf][3];
                }
        }
        __syncthreads();
        int chbase = g * 160;

        if ((MODE == 0 && yy == 1) || MODE == 2) {    // f32 ch-major path
            for (int idx = tid; idx < 160 * 128; idx += 256) {
                int n = idx >> 7, p = idx & 127;
                float v = fst[n * 132 + p];
                size_t o = (((size_t)b * COUT + chbase + n) << 12) + pix0 + p;
                if (MODE == 0) hF[o] = v + __ldg(bias + chbase + n);
                else           out[o] = hF[o] + sc * v;
            }
        }
        if (MODE <= 1) {                              // bf16 hi/lo pixel-major path
            int p = tid >> 1, half = tid & 1;
            int cb = chbase + half * 80;
            size_t row = ((size_t)(b * HW) + pix0 + p) * ldo + cofs + cb;
            uint32_t uh[40], ul[40];
#pragma unroll
            for (int m = 0; m < 40; m++) {
                int n = half * 80 + 2 * m;
                float v0 = fst[n * 132 + p], v1 = fst[(n + 1) * 132 + p];
                if (MODE == 0) {
                    v0 += __ldg(bias + chbase + n);
                    v1 += __ldg(bias + chbase + n + 1);
                }
                __nv_bfloat16 h0, l0, h1, l1;
                bsplit(v0, h0, l0); bsplit(v1, h1, l1);
                uh[m] = bpack(h0, h1); ul[m] = bpack(l0, l1);
            }
#pragma unroll
            for (int q = 0; q < 10; q++) {
                ((uint4*)(Oh + row))[q] = make_uint4(uh[4*q], uh[4*q+1], uh[4*q+2], uh[4*q+3]);
                ((uint4*)(Ol + row))[q] = make_uint4(ul[4*q], ul[4*q+1], ul[4*q+2], ul[4*q+3]);
            }
        }
        __syncthreads();
    }
}

// ---------------- launch ----------------
extern "C" void kernel_launch(void* const* d_in, const int* in_sizes, int n_in,
                              void* d_out, int out_size) {
    const float* x      = (const float*)d_in[0];
    const float* weight = (const float*)d_in[1];
    const float* bias   = (const float*)d_in[2];
    const float* w_down = (const float*)d_in[3];
    const float* w_up   = (const float*)d_in[4];
    const float* scale  = (const float*)d_in[5];
    const float* offset = (const float*)d_in[6];
    float* out = (float*)d_out;

    __nv_bfloat16 *Ach, *Acl, *Adh, *Adl, *wth, *wtl, *wdh, *wdl, *wuh, *wul, *cth, *ctl, *dnh, *dnl;
    float *hF;
    cudaGetSymbolAddress((void**)&Ach, g_Ach); cudaGetSymbolAddress((void**)&Acl, g_Acl);
    cudaGetSymbolAddress((void**)&Adh, g_Adh); cudaGetSymbolAddress((void**)&Adl, g_Adl);
    cudaGetSymbolAddress((void**)&wth, g_wth); cudaGetSymbolAddress((void**)&wtl, g_wtl);
    cudaGetSymbolAddress((void**)&wdh, g_wdh); cudaGetSymbolAddress((void**)&wdl, g_wdl);
    cudaGetSymbolAddress((void**)&wuh, g_wuh); cudaGetSymbolAddress((void**)&wul, g_wul);
    cudaGetSymbolAddress((void**)&cth, g_cth); cudaGetSymbolAddress((void**)&ctl, g_ctl);
    cudaGetSymbolAddress((void**)&dnh, g_dnh); cudaGetSymbolAddress((void**)&dnl, g_dnl);
    cudaGetSymbolAddress((void**)&hF,  g_hF);

    cudaFuncSetAttribute(im2col_fused, cudaFuncAttributeMaxDynamicSharedMemorySize, 131072);
    cudaFuncSetAttribute(gemm_mma<0>, cudaFuncAttributeMaxDynamicSharedMemorySize, SMEMB);
    cudaFuncSetAttribute(gemm_mma<1>, cudaFuncAttributeMaxDynamicSharedMemorySize, SMEMB);
    cudaFuncSetAttribute(gemm_mma<2>, cudaFuncAttributeMaxDynamicSharedMemorySize, SMEMB);

    precompute<<<(9 * HW + 255) / 256, 256>>>(offset);
    split_plain<<<(COUT * CK   + 255) / 256, 256>>>(weight, wth, wtl, COUT * CK);
    split_plain<<<(COUT * CAT2 + 255) / 256, 256>>>(w_down, wdh, wdl, COUT * CAT2);
    split_plain<<<(COUT * COUT + 255) / 256, 256>>>(w_up,   wuh, wul, COUT * COUT);

    im2col_fused<<<dim3(40, BATCH), 256, 131072>>>(x, Ach, Acl, Adh, Adl);

    // big dual GEMM: y=0 -> dconv -> cat[:,0:320]; y=1 -> conv -> cat[:,320:640] + hF
    gemm_mma<0><<<dim3(HW / 128, 2, BATCH), 256, SMEMB>>>(
        Adh, Adl, Ach, Acl, wth, wtl, CK, bias, hF, cth, ctl, CAT2, nullptr, nullptr);
    // down = w_down @ cat -> dn
    gemm_mma<1><<<dim3(HW / 128, 1, BATCH), 256, SMEMB>>>(
        cth, ctl, nullptr, nullptr, wdh, wdl, CAT2, nullptr, nullptr, dnh, dnl, COUT, nullptr, nullptr);
    // out = hF + scale * (w_up @ dn)
    gemm_mma<2><<<dim3(HW / 128, 1, BATCH), 256, SMEMB>>>(
        dnh, dnl, nullptr, nullptr, wuh, wul, COUT, nullptr, hF, nullptr, nullptr, 0, out, scale);
}

// round 6
// speedup vs baseline: 3.4191x; 1.4429x over previous
#include <cuda_runtime.h>
#include <cuda_fp16.h>
#include <cstdint>

#define BATCH 4
#define CIN   320
#define COUT  320
#define HW    4096
#define CK    2880           // K = c*9 + k (native weight layout)
#define CAT2  640
// stage: A 128x80B = 10240 ; B hi 320x80B = 25600 ; B lo 25600 ; total 61440
#define STGB  61440
#define SMEMB (2 * STGB)     // 122880

// ---------------- device scratch ----------------
__device__ __half g_Ac[(size_t)BATCH*HW*CK];           // conv im2col, fp16
__device__ __half g_Ad[(size_t)BATCH*HW*CK];           // deformable im2col, fp16
__device__ __half g_wth[COUT*CK],   g_wtl[COUT*CK];    // weight hi/lo
__device__ __half g_wdh[COUT*CAT2], g_wdl[COUT*CAT2];
__device__ __half g_wuh[COUT*COUT], g_wul[COUT*COUT];
__device__ __half g_ct[(size_t)BATCH*HW*CAT2];         // cat = [dconv, h], fp16
__device__ __half g_dn[(size_t)BATCH*HW*COUT];         // down, fp16
__device__ float  g_hF[(size_t)BATCH*COUT*HW];         // h (exact-ish f32, ch-major)
__device__ int    g_ci[9*HW];
__device__ float  g_cw[9*HW];
__device__ int4   g_idf[9*HW];
__device__ float4 g_wdf[9*HW];

// ---------------- helpers ----------------
__device__ __forceinline__ uint32_t smem_u32(const void* p) {
    uint32_t a;
    asm("{ .reg .u64 t; cvta.to.shared.u64 t, %1; cvt.u32.u64 %0, t; }" : "=r"(a) : "l"(p));
    return a;
}
__device__ __forceinline__ void cpa16(uint32_t dst, const void* src) {
    asm volatile("cp.async.cg.shared.global [%0], [%1], 16;" :: "r"(dst), "l"(src));
}
#define LDM4(r, addr) \
    asm volatile("ldmatrix.sync.aligned.m8n8.x4.shared.b16 {%0,%1,%2,%3}, [%4];" \
        : "=r"((r)[0]), "=r"((r)[1]), "=r"((r)[2]), "=r"((r)[3]) : "r"(addr))
#define MMA_F16(c, a, bq) \
    asm volatile("mma.sync.aligned.m16n8k16.row.col.f32.f16.f16.f32 " \
        "{%0,%1,%2,%3}, {%4,%5,%6,%7}, {%8,%9}, {%0,%1,%2,%3};" \
        : "+f"((c)[0]), "+f"((c)[1]), "+f"((c)[2]), "+f"((c)[3]) \
        : "r"((a)[0]), "r"((a)[1]), "r"((a)[2]), "r"((a)[3]), "r"((bq)[0]), "r"((bq)[1]))

__device__ __forceinline__ uint32_t hpack(__half a, __half b) {
    return (uint32_t)__half_as_ushort(a) | ((uint32_t)__half_as_ushort(b) << 16);
}

// ---------------- table precompute ----------------
__global__ void precompute(const float* __restrict__ off) {
    int t = blockIdx.x * 256 + threadIdx.x;
    if (t >= 9 * HW) return;
    int k = t >> 12, p = t & 4095;
    int r = p >> 6, c = p & 63;
    int rr = r + k / 3 - 1, qq = c + k % 3 - 1;
    bool vb = (rr >= 0 && rr < 64 && qq >= 0 && qq < 64);
    g_ci[t] = vb ? rr * 64 + qq : 0;
    g_cw[t] = vb ? 1.f : 0.f;
    float dy = off[((k*2+0) << 12) + p];
    float dx = off[((k*2+1) << 12) + p];
    float py = (float)rr + dy, px = (float)qq + dx;
    float y0f = floorf(py), x0f = floorf(px);
    int y0 = (int)y0f, x0 = (int)x0f;
    float wy = py - y0f, wx = px - x0f;
    float wv[4] = { (1.f-wy)*(1.f-wx), (1.f-wy)*wx, wy*(1.f-wx), wy*wx };
    int   idx[4]; float wgt[4];
#pragma unroll
    for (int j = 0; j < 4; j++) {
        int yy = y0 + (j >> 1), xx = x0 + (j & 1);
        bool ok = (yy >= 0 && yy < 64 && xx >= 0 && xx < 64);
        idx[j] = (min(max(yy,0),63) << 6) + min(max(xx,0),63);
        wgt[j] = ok ? wv[j] : 0.f;
    }
    g_idf[t] = make_int4(idx[0], idx[1], idx[2], idx[3]);
    g_wdf[t] = make_float4(wgt[0], wgt[1], wgt[2], wgt[3]);
}

// weight split: hi = fp16(w), lo = fp16(w - hi)
__global__ void split_w(const float* __restrict__ s, __half* hi, __half* lo, int n) {
    int i = blockIdx.x * 256 + threadIdx.x;
    if (i >= n) return;
    float v = s[i];
    __half h = __float2half_rn(v);
    hi[i] = h;
    lo[i] = __float2half_rn(v - __half2float(h));
}

// ---------------- fused im2col (conv + deformable), K = c*9+k, fp16 ----------------
__device__ __forceinline__ void store72(__half* __restrict__ H, const float* tv) {
#pragma unroll
    for (int q = 0; q < 9; q++) {
        uint32_t hh[4];
#pragma unroll
        for (int m = 0; m < 4; m++)
            hh[m] = hpack(__float2half_rn(tv[q*8 + 2*m]), __float2half_rn(tv[q*8 + 2*m + 1]));
        ((uint4*)H)[q] = make_uint4(hh[0], hh[1], hh[2], hh[3]);
    }
}

__global__ __launch_bounds__(256) void im2col_fused(
    const float* __restrict__ x,
    __half* __restrict__ Ac, __half* __restrict__ Ad)
{
    extern __shared__ float pl[];   // 8 channel planes = 128KB
    int b  = blockIdx.y;
    int c0 = blockIdx.x * 8;
    for (int idx = threadIdx.x; idx < 8 * 4096; idx += 256)
        pl[idx] = x[(((size_t)b * CIN + c0) << 12) + idx];
    __syncthreads();

    for (int p = threadIdx.x; p < 4096; p += 256) {
        float tv[72];
        size_t o = ((size_t)(b * HW) + p) * CK + (size_t)c0 * 9;
#pragma unroll
        for (int k = 0; k < 9; k++) {
            int   ci = g_ci[(k << 12) + p];
            float cw = g_cw[(k << 12) + p];
#pragma unroll
            for (int c = 0; c < 8; c++)
                tv[c*9 + k] = cw * pl[(c << 12) + ci];
        }
        store72(Ac + o, tv);
#pragma unroll
        for (int k = 0; k < 9; k++) {
            int4   di = g_idf[(k << 12) + p];
            float4 dw = g_wdf[(k << 12) + p];
#pragma unroll
            for (int c = 0; c < 8; c++) {
                const float* q = pl + (c << 12);
                tv[c*9 + k] = dw.x*q[di.x] + dw.y*q[di.y] + dw.z*q[di.z] + dw.w*q[di.w];
            }
        }
        store72(Ad + o, tv);
    }
}

// ---------------- HMMA GEMM: D[128 pix][320 ch] = sum_K A[pix][K]*(hiB+loB)[ch][K] ----------------
// MODE 0 (big dual): grid.y=0 -> A=def -> cat[:,0:320]; grid.y=1 -> A=conv -> cat[:,320:640] + hF. +bias.
// MODE 1 (down): A=cat (K=640) -> dn.
// MODE 2 (up):   A=dn (K=320) -> out = hF + scale*acc (f32 ch-major).
template<int MODE>
__global__ void __launch_bounds__(256, 1) gemm_mma(
    const __half* __restrict__ A0, const __half* __restrict__ A1,
    const __half* __restrict__ Bh, const __half* __restrict__ Bl,
    int K, const float* __restrict__ bias, float* __restrict__ hF,
    __half* __restrict__ O, int ldo,
    float* __restrict__ out, const float* __restrict__ scalep)
{
    extern __shared__ char smem[];
    uint32_t sb = smem_u32(smem);
    float* fst = (float*)smem;                  // epilogue stage [160][132]
    int tid = threadIdx.x;
    int b = blockIdx.z;
    int pix0 = blockIdx.x * 128;
    int yy = (MODE == 0) ? blockIdx.y : 0;
    int NCH = K >> 5;

    const __half* Ab = ((MODE == 0 && yy == 1) ? A1 : A0) + (size_t)(b * HW + pix0) * K;
    int cofs = (MODE == 0 && yy == 1) ? 320 : 0;

    int w = tid >> 5, lane = tid & 31;
    int m0 = (w & 3) * 32;
    int ng = w >> 2;                  // 0 or 1: channel group base ng*160
    int a_r = (lane & 7) + ((lane >> 3) & 1) * 8;
    int a_c = ((lane >> 4) & 1) * 16;
    int b_r = (lane & 7) + ((lane >> 4) & 1) * 8;
    int b_c = ((lane >> 3) & 1) * 16;

    float acc[2][20][4];
#pragma unroll
    for (int i = 0; i < 2; i++)
#pragma unroll
        for (int j = 0; j < 20; j++)
#pragma unroll
            for (int q = 0; q < 4; q++) acc[i][j][q] = 0.f;

    auto load_stage = [&](int ci) {
        uint32_t st = sb + (uint32_t)(ci & 1) * STGB;
        int k0 = ci << 5;
        {                                        // A: 128 rows x 64B
            int r = tid >> 1, j = tid & 1;
            cpa16(st + r * 80 + j * 32,      Ab + (size_t)r * K + k0 + j * 16);
            cpa16(st + r * 80 + j * 32 + 16, Ab + (size_t)r * K + k0 + j * 16 + 8);
        }
#pragma unroll
        for (int it = 0; it < 5; it++) {        // B: 320 rows x 64B (hi & lo)
            int idx = tid + it * 256;
            int r = idx >> 2, j = idx & 3;
            cpa16(st + 10240 + r * 80 + j * 16, Bh + (size_t)r * K + k0 + j * 8);
            cpa16(st + 35840 + r * 80 + j * 16, Bl + (size_t)r * K + k0 + j * 8);
        }
        asm volatile("cp.async.commit_group;" ::: "memory");
    };

    load_stage(0);
    for (int i = 0; i < NCH; i++) {
        if (i + 1 < NCH) {
            load_stage(i + 1);
            asm volatile("cp.async.wait_group 1;" ::: "memory");
        } else {
            asm volatile("cp.async.wait_group 0;" ::: "memory");
        }
        __syncthreads();
        uint32_t st = sb + (uint32_t)(i & 1) * STGB;
#pragma unroll
        for (int kk = 0; kk < 2; kk++) {
            uint32_t ah[2][4];
#pragma unroll
            for (int mf = 0; mf < 2; mf++) {
                uint32_t ad = st + (uint32_t)(m0 + mf * 16 + a_r) * 80 + kk * 32 + a_c;
                LDM4(ah[mf], ad);
            }
#pragma unroll
            for (int np = 0; np < 10; np++) {
                uint32_t bh[4], bl[4];
                uint32_t bd = st + 10240 + (uint32_t)(ng * 160 + np * 16 + b_r) * 80 + kk * 32 + b_c;
                LDM4(bh, bd);
                LDM4(bl, bd + 25600);
#pragma unroll
                for (int mf = 0; mf < 2; mf++)
#pragma unroll
                    for (int h = 0; h < 2; h++) {
                        float* c = acc[mf][np * 2 + h];
                        MMA_F16(c, ah[mf], bh + 2 * h);
                        MMA_F16(c, ah[mf], bl + 2 * h);
                    }
            }
        }
        __syncthreads();
    }

    // ---- epilogue: 2 chunks of 160 channels staged via smem [160][132] ----
    float sc = (MODE == 2) ? *scalep : 0.f;
    for (int g = 0; g < 2; g++) {
        if (ng == g) {
#pragma unroll
            for (int mf = 0; mf < 2; mf++)
#pragma unroll
                for (int nf = 0; nf < 20; nf++) {
                    int pr = m0 + mf * 16 + (lane >> 2);
                    int nc = nf * 8 + 2 * (lane & 3);
                    fst[nc * 132 + pr]           = acc[mf][nf][0];
                    fst[(nc + 1) * 132 + pr]     = acc[mf][nf][1];
                    fst[nc * 132 + pr + 8]       = acc[mf][nf][2];
                    fst[(nc + 1) * 132 + pr + 8] = acc[mf][nf][3];
                }
        }
        __syncthreads();
        int chbase = g * 160;

        if ((MODE == 0 && yy == 1) || MODE == 2) {    // f32 ch-major path
            for (int idx = tid; idx < 160 * 128; idx += 256) {
                int n = idx >> 7, p = idx & 127;
                float v = fst[n * 132 + p];
                size_t o = (((size_t)b * COUT + chbase + n) << 12) + pix0 + p;
                if (MODE == 0) hF[o] = v + __ldg(bias + chbase + n);
                else           out[o] = hF[o] + sc * v;
            }
        }
        if (MODE <= 1) {                              // fp16 pixel-major path
            int p = tid >> 1, hf2 = tid & 1;
            int cb = chbase + hf2 * 80;
            size_t row = ((size_t)(b * HW) + pix0 + p) * ldo + cofs + cb;
            uint32_t uh[40];
#pragma unroll
            for (int m = 0; m < 40; m++) {
                int n = hf2 * 80 + 2 * m;
                float v0 = fst[n * 132 + p], v1 = fst[(n + 1) * 132 + p];
                if (MODE == 0) {
                    v0 += __ldg(bias + chbase + n);
                    v1 += __ldg(bias + chbase + n + 1);
                }
                uh[m] = hpack(__float2half_rn(v0), __float2half_rn(v1));
            }
#pragma unroll
            for (int q = 0; q < 10; q++)
                ((uint4*)(O + row))[q] = make_uint4(uh[4*q], uh[4*q+1], uh[4*q+2], uh[4*q+3]);
        }
        __syncthreads();
    }
}

// ---------------- launch ----------------
extern "C" void kernel_launch(void* const* d_in, const int* in_sizes, int n_in,
                              void* d_out, int out_size) {
    const float* x      = (const float*)d_in[0];
    const float* weight = (const float*)d_in[1];
    const float* bias   = (const float*)d_in[2];
    const float* w_down = (const float*)d_in[3];
    const float* w_up   = (const float*)d_in[4];
    const float* scale  = (const float*)d_in[5];
    const float* offset = (const float*)d_in[6];
    float* out = (float*)d_out;

    __half *Ac, *Ad, *wth, *wtl, *wdh, *wdl, *wuh, *wul, *ct, *dn;
    float *hF;
    cudaGetSymbolAddress((void**)&Ac,  g_Ac);  cudaGetSymbolAddress((void**)&Ad,  g_Ad);
    cudaGetSymbolAddress((void**)&wth, g_wth); cudaGetSymbolAddress((void**)&wtl, g_wtl);
    cudaGetSymbolAddress((void**)&wdh, g_wdh); cudaGetSymbolAddress((void**)&wdl, g_wdl);
    cudaGetSymbolAddress((void**)&wuh, g_wuh); cudaGetSymbolAddress((void**)&wul, g_wul);
    cudaGetSymbolAddress((void**)&ct,  g_ct);  cudaGetSymbolAddress((void**)&dn,  g_dn);
    cudaGetSymbolAddress((void**)&hF,  g_hF);

    cudaFuncSetAttribute(im2col_fused, cudaFuncAttributeMaxDynamicSharedMemorySize, 131072);
    cudaFuncSetAttribute(gemm_mma<0>, cudaFuncAttributeMaxDynamicSharedMemorySize, SMEMB);
    cudaFuncSetAttribute(gemm_mma<1>, cudaFuncAttributeMaxDynamicSharedMemorySize, SMEMB);
    cudaFuncSetAttribute(gemm_mma<2>, cudaFuncAttributeMaxDynamicSharedMemorySize, SMEMB);

    precompute<<<(9 * HW + 255) / 256, 256>>>(offset);
    split_w<<<(COUT * CK   + 255) / 256, 256>>>(weight, wth, wtl, COUT * CK);
    split_w<<<(COUT * CAT2 + 255) / 256, 256>>>(w_down, wdh, wdl, COUT * CAT2);
    split_w<<<(COUT * COUT + 255) / 256, 256>>>(w_up,   wuh, wul, COUT * COUT);

    im2col_fused<<<dim3(40, BATCH), 256, 131072>>>(x, Ac, Ad);

    // big dual GEMM: y=0 -> dconv -> cat[:,0:320]; y=1 -> conv -> cat[:,320:640] + hF
    gemm_mma<0><<<dim3(HW / 128, 2, BATCH), 256, SMEMB>>>(
        Ad, Ac, wth, wtl, CK, bias, hF, ct, CAT2, nullptr, nullptr);
    // down = w_down @ cat -> dn
    gemm_mma<1><<<dim3(HW / 128, 1, BATCH), 256, SMEMB>>>(
        ct, nullptr, wdh, wdl, CAT2, nullptr, nullptr, dn, COUT, nullptr, nullptr);
    // out = hF + scale * (w_up @ dn)
    gemm_mma<2><<<dim3(HW / 128, 1, BATCH), 256, SMEMB>>>(
        dn, nullptr, wuh, wul, COUT, nullptr, hF, nullptr, 0, out, scale);
}

// round 7
// speedup vs baseline: 4.5270x; 1.3240x over previous
#include <cuda_runtime.h>
#include <cuda_fp16.h>
#include <cstdint>

#define BATCH 4
#define CIN   320
#define COUT  320
#define HW    4096
#define CK    2880           // K = c*9 + k (native weight layout)
#define CAT2  640
// stage: A 128x80B = 10240 ; B 320x80B = 25600 ; total 35840
#define STGB  35840
#define SMEMB 84480          // max(2*STGB=71680, epilogue stage 160*132*4=84480)

// ---------------- device scratch ----------------
__device__ __half g_Ac[(size_t)BATCH*HW*CK];           // conv im2col, fp16
__device__ __half g_Ad[(size_t)BATCH*HW*CK];           // deformable im2col, fp16
__device__ __half g_wt[COUT*CK];                       // weight fp16
__device__ __half g_wd[COUT*CAT2];
__device__ __half g_wu[COUT*COUT];
__device__ __half g_ct[(size_t)BATCH*HW*CAT2];         // cat = [dconv, h], fp16
__device__ __half g_dn[(size_t)BATCH*HW*COUT];         // down, fp16
__device__ float  g_hF[(size_t)BATCH*COUT*HW];         // h (f32, ch-major)
__device__ int    g_ci[9*HW];
__device__ float  g_cw[9*HW];
__device__ int4   g_idf[9*HW];
__device__ float4 g_wdf[9*HW];

// ---------------- helpers ----------------
__device__ __forceinline__ uint32_t smem_u32(const void* p) {
    uint32_t a;
    asm("{ .reg .u64 t; cvta.to.shared.u64 t, %1; cvt.u32.u64 %0, t; }" : "=r"(a) : "l"(p));
    return a;
}
__device__ __forceinline__ void cpa16(uint32_t dst, const void* src) {
    asm volatile("cp.async.cg.shared.global [%0], [%1], 16;" :: "r"(dst), "l"(src));
}
#define LDM4(r, addr) \
    asm volatile("ldmatrix.sync.aligned.m8n8.x4.shared.b16 {%0,%1,%2,%3}, [%4];" \
        : "=r"((r)[0]), "=r"((r)[1]), "=r"((r)[2]), "=r"((r)[3]) : "r"(addr))
#define MMA_F16(c, a, bq) \
    asm volatile("mma.sync.aligned.m16n8k16.row.col.f32.f16.f16.f32 " \
        "{%0,%1,%2,%3}, {%4,%5,%6,%7}, {%8,%9}, {%0,%1,%2,%3};" \
        : "+f"((c)[0]), "+f"((c)[1]), "+f"((c)[2]), "+f"((c)[3]) \
        : "r"((a)[0]), "r"((a)[1]), "r"((a)[2]), "r"((a)[3]), "r"((bq)[0]), "r"((bq)[1]))

__device__ __forceinline__ uint32_t hpack(__half a, __half b) {
    return (uint32_t)__half_as_ushort(a) | ((uint32_t)__half_as_ushort(b) << 16);
}

// ---------------- table precompute ----------------
__global__ void precompute(const float* __restrict__ off) {
    int t = blockIdx.x * 256 + threadIdx.x;
    if (t >= 9 * HW) return;
    int k = t >> 12, p = t & 4095;
    int r = p >> 6, c = p & 63;
    int rr = r + k / 3 - 1, qq = c + k % 3 - 1;
    bool vb = (rr >= 0 && rr < 64 && qq >= 0 && qq < 64);
    g_ci[t] = vb ? rr * 64 + qq : 0;
    g_cw[t] = vb ? 1.f : 0.f;
    float dy = off[((k*2+0) << 12) + p];
    float dx = off[((k*2+1) << 12) + p];
    float py = (float)rr + dy, px = (float)qq + dx;
    float y0f = floorf(py), x0f = floorf(px);
    int y0 = (int)y0f, x0 = (int)x0f;
    float wy = py - y0f, wx = px - x0f;
    float wv[4] = { (1.f-wy)*(1.f-wx), (1.f-wy)*wx, wy*(1.f-wx), wy*wx };
    int   idx[4]; float wgt[4];
#pragma unroll
    for (int j = 0; j < 4; j++) {
        int yy = y0 + (j >> 1), xx = x0 + (j & 1);
        bool ok = (yy >= 0 && yy < 64 && xx >= 0 && xx < 64);
        idx[j] = (min(max(yy,0),63) << 6) + min(max(xx,0),63);
        wgt[j] = ok ? wv[j] : 0.f;
    }
    g_idf[t] = make_int4(idx[0], idx[1], idx[2], idx[3]);
    g_wdf[t] = make_float4(wgt[0], wgt[1], wgt[2], wgt[3]);
}

__global__ void to_fp16(const float* __restrict__ s, __half* d, int n) {
    int i = blockIdx.x * 256 + threadIdx.x;
    if (i < n) d[i] = __float2half_rn(s[i]);
}

// ---------------- fused im2col (conv + deformable), K = c*9+k, fp16 ----------------
__device__ __forceinline__ void store72(__half* __restrict__ H, const float* tv) {
#pragma unroll
    for (int q = 0; q < 9; q++) {
        uint32_t hh[4];
#pragma unroll
        for (int m = 0; m < 4; m++)
            hh[m] = hpack(__float2half_rn(tv[q*8 + 2*m]), __float2half_rn(tv[q*8 + 2*m + 1]));
        ((uint4*)H)[q] = make_uint4(hh[0], hh[1], hh[2], hh[3]);
    }
}

__global__ __launch_bounds__(256) void im2col_fused(
    const float* __restrict__ x,
    __half* __restrict__ Ac, __half* __restrict__ Ad)
{
    extern __shared__ float pl[];   // 8 channel planes = 128KB
    int b  = blockIdx.y;
    int c0 = blockIdx.x * 8;
    for (int idx = threadIdx.x; idx < 8 * 4096; idx += 256)
        pl[idx] = x[(((size_t)b * CIN + c0) << 12) + idx];
    __syncthreads();

    for (int p = threadIdx.x; p < 4096; p += 256) {
        float tv[72];
        size_t o = ((size_t)(b * HW) + p) * CK + (size_t)c0 * 9;
#pragma unroll
        for (int k = 0; k < 9; k++) {
            int   ci = g_ci[(k << 12) + p];
            float cw = g_cw[(k << 12) + p];
#pragma unroll
            for (int c = 0; c < 8; c++)
                tv[c*9 + k] = cw * pl[(c << 12) + ci];
        }
        store72(Ac + o, tv);
#pragma unroll
        for (int k = 0; k < 9; k++) {
            int4   di = g_idf[(k << 12) + p];
            float4 dw = g_wdf[(k << 12) + p];
#pragma unroll
            for (int c = 0; c < 8; c++) {
                const float* q = pl + (c << 12);
                tv[c*9 + k] = dw.x*q[di.x] + dw.y*q[di.y] + dw.z*q[di.z] + dw.w*q[di.w];
            }
        }
        store72(Ad + o, tv);
    }
}

// ---------------- HMMA GEMM: D[128 pix][320 ch] = sum_K A[pix][K]*B[ch][K], fp16 ----------------
// MODE 0 (big dual): grid.y=0 -> A=def -> cat[:,0:320]; grid.y=1 -> A=conv -> cat[:,320:640] + hF. +bias.
// MODE 1 (down): A=cat (K=640) -> dn.
// MODE 2 (up):   A=dn (K=320) -> out = hF + scale*acc (f32 ch-major).
template<int MODE>
__global__ void __launch_bounds__(256, 1) gemm_mma(
    const __half* __restrict__ A0, const __half* __restrict__ A1,
    const __half* __restrict__ B,
    int K, const float* __restrict__ bias, float* __restrict__ hF,
    __half* __restrict__ O, int ldo,
    float* __restrict__ out, const float* __restrict__ scalep)
{
    extern __shared__ char smem[];
    uint32_t sb = smem_u32(smem);
    float* fst = (float*)smem;                  // epilogue stage [160][132]
    int tid = threadIdx.x;
    int b = blockIdx.z;
    int pix0 = blockIdx.x * 128;
    int yy = (MODE == 0) ? blockIdx.y : 0;
    int NCH = K >> 5;

    const __half* Ab = ((MODE == 0 && yy == 1) ? A1 : A0) + (size_t)(b * HW + pix0) * K;
    int cofs = (MODE == 0 && yy == 1) ? 320 : 0;

    int w = tid >> 5, lane = tid & 31;
    int m0 = (w & 3) * 32;
    int ng = w >> 2;                  // 0 or 1: channel group base ng*160
    int a_r = (lane & 7) + ((lane >> 3) & 1) * 8;
    int a_c = ((lane >> 4) & 1) * 16;
    int b_r = (lane & 7) + ((lane >> 4) & 1) * 8;
    int b_c = ((lane >> 3) & 1) * 16;

    float acc[2][20][4];
#pragma unroll
    for (int i = 0; i < 2; i++)
#pragma unroll
        for (int j = 0; j < 20; j++)
#pragma unroll
            for (int q = 0; q < 4; q++) acc[i][j][q] = 0.f;

    auto load_stage = [&](int ci) {
        uint32_t st = sb + (uint32_t)(ci & 1) * STGB;
        int k0 = ci << 5;
        {                                        // A: 128 rows x 64B
            int r = tid >> 1, j = tid & 1;
            cpa16(st + r * 80 + j * 32,      Ab + (size_t)r * K + k0 + j * 16);
            cpa16(st + r * 80 + j * 32 + 16, Ab + (size_t)r * K + k0 + j * 16 + 8);
        }
#pragma unroll
        for (int it = 0; it < 5; it++) {        // B: 320 rows x 64B
            int idx = tid + it * 256;
            int r = idx >> 2, j = idx & 3;
            cpa16(st + 10240 + r * 80 + j * 16, B + (size_t)r * K + k0 + j * 8);
        }
        asm volatile("cp.async.commit_group;" ::: "memory");
    };

    load_stage(0);
    for (int i = 0; i < NCH; i++) {
        if (i + 1 < NCH) {
            load_stage(i + 1);
            asm volatile("cp.async.wait_group 1;" ::: "memory");
        } else {
            asm volatile("cp.async.wait_group 0;" ::: "memory");
        }
        __syncthreads();
        uint32_t st = sb + (uint32_t)(i & 1) * STGB;
#pragma unroll
        for (int kk = 0; kk < 2; kk++) {
            uint32_t ah[2][4];
#pragma unroll
            for (int mf = 0; mf < 2; mf++) {
                uint32_t ad = st + (uint32_t)(m0 + mf * 16 + a_r) * 80 + kk * 32 + a_c;
                LDM4(ah[mf], ad);
            }
#pragma unroll
            for (int np = 0; np < 10; np++) {
                uint32_t bh[4];
                uint32_t bd = st + 10240 + (uint32_t)(ng * 160 + np * 16 + b_r) * 80 + kk * 32 + b_c;
                LDM4(bh, bd);
#pragma unroll
                for (int mf = 0; mf < 2; mf++)
#pragma unroll
                    for (int h = 0; h < 2; h++)
                        MMA_F16(acc[mf][np * 2 + h], ah[mf], bh + 2 * h);
            }
        }
        __syncthreads();
    }

    // ---- epilogue: 2 chunks of 160 channels staged via smem [160][132] ----
    float sc = (MODE == 2) ? *scalep : 0.f;
    for (int g = 0; g < 2; g++) {
        if (ng == g) {
#pragma unroll
            for (int mf = 0; mf < 2; mf++)
#pragma unroll
                for (int nf = 0; nf < 20; nf++) {
                    int pr = m0 + mf * 16 + (lane >> 2);
                    int nc = nf * 8 + 2 * (lane & 3);
                    fst[nc * 132 + pr]           = acc[mf][nf][0];
                    fst[(nc + 1) * 132 + pr]     = acc[mf][nf][1];
                    fst[nc * 132 + pr + 8]       = acc[mf][nf][2];
                    fst[(nc + 1) * 132 + pr + 8] = acc[mf][nf][3];
                }
        }
        __syncthreads();
        int chbase = g * 160;

        if ((MODE == 0 && yy == 1) || MODE == 2) {    // f32 ch-major path
            for (int idx = tid; idx < 160 * 128; idx += 256) {
                int n = idx >> 7, p = idx & 127;
                float v = fst[n * 132 + p];
                size_t o = (((size_t)b * COUT + chbase + n) << 12) + pix0 + p;
                if (MODE == 0) hF[o] = v + __ldg(bias + chbase + n);
                else           out[o] = hF[o] + sc * v;
            }
        }
        if (MODE <= 1) {                              // fp16 pixel-major path
            int p = tid >> 1, hf2 = tid & 1;
            int cb = chbase + hf2 * 80;
            size_t row = ((size_t)(b * HW) + pix0 + p) * ldo + cofs + cb;
            uint32_t uh[40];
#pragma unroll
            for (int m = 0; m < 40; m++) {
                int n = hf2 * 80 + 2 * m;
                float v0 = fst[n * 132 + p], v1 = fst[(n + 1) * 132 + p];
                if (MODE == 0) {
                    v0 += __ldg(bias + chbase + n);
                    v1 += __ldg(bias + chbase + n + 1);
                }
                uh[m] = hpack(__float2half_rn(v0), __float2half_rn(v1));
            }
#pragma unroll
            for (int q = 0; q < 10; q++)
                ((uint4*)(O + row))[q] = make_uint4(uh[4*q], uh[4*q+1], uh[4*q+2], uh[4*q+3]);
        }
        __syncthreads();
    }
}

// ---------------- launch ----------------
extern "C" void kernel_launch(void* const* d_in, const int* in_sizes, int n_in,
                              void* d_out, int out_size) {
    const float* x      = (const float*)d_in[0];
    const float* weight = (const float*)d_in[1];
    const float* bias   = (const float*)d_in[2];
    const float* w_down = (const float*)d_in[3];
    const float* w_up   = (const float*)d_in[4];
    const float* scale  = (const float*)d_in[5];
    const float* offset = (const float*)d_in[6];
    float* out = (float*)d_out;

    __half *Ac, *Ad, *wt, *wd, *wu, *ct, *dn;
    float *hF;
    cudaGetSymbolAddress((void**)&Ac, g_Ac); cudaGetSymbolAddress((void**)&Ad, g_Ad);
    cudaGetSymbolAddress((void**)&wt, g_wt); cudaGetSymbolAddress((void**)&wd, g_wd);
    cudaGetSymbolAddress((void**)&wu, g_wu);
    cudaGetSymbolAddress((void**)&ct, g_ct); cudaGetSymbolAddress((void**)&dn, g_dn);
    cudaGetSymbolAddress((void**)&hF, g_hF);

    cudaFuncSetAttribute(im2col_fused, cudaFuncAttributeMaxDynamicSharedMemorySize, 131072);
    cudaFuncSetAttribute(gemm_mma<0>, cudaFuncAttributeMaxDynamicSharedMemorySize, SMEMB);
    cudaFuncSetAttribute(gemm_mma<1>, cudaFuncAttributeMaxDynamicSharedMemorySize, SMEMB);
    cudaFuncSetAttribute(gemm_mma<2>, cudaFuncAttributeMaxDynamicSharedMemorySize, SMEMB);

    precompute<<<(9 * HW + 255) / 256, 256>>>(offset);
    to_fp16<<<(COUT * CK   + 255) / 256, 256>>>(weight, wt, COUT * CK);
    to_fp16<<<(COUT * CAT2 + 255) / 256, 256>>>(w_down, wd, COUT * CAT2);
    to_fp16<<<(COUT * COUT + 255) / 256, 256>>>(w_up,   wu, COUT * COUT);

    im2col_fused<<<dim3(40, BATCH), 256, 131072>>>(x, Ac, Ad);

    // big dual GEMM: y=0 -> dconv -> cat[:,0:320]; y=1 -> conv -> cat[:,320:640] + hF
    gemm_mma<0><<<dim3(HW / 128, 2, BATCH), 256, SMEMB>>>(
        Ad, Ac, wt, CK, bias, hF, ct, CAT2, nullptr, nullptr);
    // down = w_down @ cat -> dn
    gemm_mma<1><<<dim3(HW / 128, 1, BATCH), 256, SMEMB>>>(
        ct, nullptr, wd, CAT2, nullptr, nullptr, dn, COUT, nullptr, nullptr);
    // out = hF + scale * (w_up @ dn)
    gemm_mma<2><<<dim3(HW / 128, 1, BATCH), 256, SMEMB>>>(
        dn, nullptr, wu, COUT, nullptr, hF, nullptr, 0, out, scale);
}